// round 1
// baseline (speedup 1.0000x reference)
#include <cuda_runtime.h>
#include <math.h>

// Problem constants
#define T_    1024
#define B_    8
#define E_    512
#define H_    8
#define D_    64
#define BH_   64          // B*H
#define TB_   8192        // T*B
#define SCALE 0.125f      // D^-0.5

#define HEADS 4194304u    // 64*1024*64   (one of q/k/v, one component)
#define SOFF  67108864u   // 64*1024*1024 (S scratch per component)
#define ATT   4194304u    // 8192*512
#define OUT_I 4194304u    // imag offset of out stack in d_out
#define AW0   8388608u    // aw region start in d_out
#define AWI   16777216u   // aw imag start in d_out

// -------- scratch (static __device__ arrays: allocation-free per harness rules) -----
__device__ float g_hr[3u * HEADS];   // [part(q,k,v)][bh][t][d] real   48MB
__device__ float g_hi[3u * HEADS];   // imag                            48MB
__device__ float g_S[2u * SOFF];     // [comp][bh][t][s] scores -> probs 512MB
__device__ float g_attn[2u * ATT];   // [comp][t*B+b][E] attn output     32MB

// ============================================================================
// Complex GEMM: C = A @ B^T (+bias), A:[M,K], B:[N,K] both row-major.
//   y_r = xr@Wr^T - xi@Wi^T + br ;  y_i = xi@Wr^T + xr@Wi^T + bi
// 64x64 tile, BK=16, 256 threads, 4x4 microtile.
// epi==0: write Cr/Ci (ld = N).  epi==1: scatter into g_hr/g_hi head layout.
// Ar==nullptr means A = g_attn (real/imag halves).
// ============================================================================
__global__ __launch_bounds__(256)
void cgemm64(const float* __restrict__ Ar, const float* __restrict__ Ai,
             const float* __restrict__ Br, const float* __restrict__ Bi,
             const float* __restrict__ bias_r, const float* __restrict__ bias_i,
             float* __restrict__ Cr, float* __restrict__ Ci,
             int N, int K, int epi)
{
    __shared__ float As_r[16][65], As_i[16][65], Bs_r[16][65], Bs_i[16][65];

    if (Ar == nullptr) { Ar = g_attn; Ai = g_attn + ATT; }

    const int tid  = threadIdx.x;
    const int tx4  = (tid & 15) * 4;
    const int ty4  = (tid >> 4) * 4;
    const int row0 = blockIdx.y * 64;
    const int col0 = blockIdx.x * 64;
    const int lr   = tid >> 2;         // 0..63
    const int lk   = (tid & 3) * 4;    // 0,4,8,12

    const float* pAr = Ar + (size_t)(row0 + lr) * K + lk;
    const float* pAi = Ai + (size_t)(row0 + lr) * K + lk;
    const float* pBr = Br + (size_t)(col0 + lr) * K + lk;
    const float* pBi = Bi + (size_t)(col0 + lr) * K + lk;

    float accr[4][4] = {}, acci[4][4] = {};

    for (int kt = 0; kt < K; kt += 16) {
        float4 va_r = *(const float4*)(pAr + kt);
        float4 va_i = *(const float4*)(pAi + kt);
        float4 vb_r = *(const float4*)(pBr + kt);
        float4 vb_i = *(const float4*)(pBi + kt);
        As_r[lk+0][lr]=va_r.x; As_r[lk+1][lr]=va_r.y; As_r[lk+2][lr]=va_r.z; As_r[lk+3][lr]=va_r.w;
        As_i[lk+0][lr]=va_i.x; As_i[lk+1][lr]=va_i.y; As_i[lk+2][lr]=va_i.z; As_i[lk+3][lr]=va_i.w;
        Bs_r[lk+0][lr]=vb_r.x; Bs_r[lk+1][lr]=vb_r.y; Bs_r[lk+2][lr]=vb_r.z; Bs_r[lk+3][lr]=vb_r.w;
        Bs_i[lk+0][lr]=vb_i.x; Bs_i[lk+1][lr]=vb_i.y; Bs_i[lk+2][lr]=vb_i.z; Bs_i[lk+3][lr]=vb_i.w;
        __syncthreads();

        #pragma unroll
        for (int kk = 0; kk < 16; kk++) {
            float arf[4], aif[4], brf[4], bif[4];
            #pragma unroll
            for (int u = 0; u < 4; u++) {
                arf[u] = As_r[kk][ty4+u];  aif[u] = As_i[kk][ty4+u];
                brf[u] = Bs_r[kk][tx4+u];  bif[u] = Bs_i[kk][tx4+u];
            }
            #pragma unroll
            for (int i = 0; i < 4; i++)
                #pragma unroll
                for (int j = 0; j < 4; j++) {
                    accr[i][j] += arf[i]*brf[j] - aif[i]*bif[j];
                    acci[i][j] += aif[i]*brf[j] + arf[i]*bif[j];
                }
        }
        __syncthreads();
    }

    #pragma unroll
    for (int i = 0; i < 4; i++) {
        int m = row0 + ty4 + i;
        #pragma unroll
        for (int j = 0; j < 4; j++) {
            int n = col0 + tx4 + j;
            float vr = accr[i][j] + bias_r[n];
            float vi = acci[i][j] + bias_i[n];
            if (epi == 0) {
                Cr[(size_t)m * N + n] = vr;
                Ci[(size_t)m * N + n] = vi;
            } else {
                // m = t*B + b ; n = part*512 + h*64 + d  -> g_h[part][b*H+h][t][d]
                int t = m >> 3, b = m & 7;
                int part = n >> 9;
                int e = n & 511;
                int h = e >> 6, d = e & 63;
                size_t dst = (size_t)part * HEADS
                           + (size_t)((b * 8 + h) * 1024 + t) * 64 + d;
                g_hr[dst] = vr;
                g_hi[dst] = vi;
            }
        }
    }
}

// ============================================================================
// Fused attention per (bh, 64-row q-tile).
// Pass 1: S_r = qr.kr + qi.ki, S_i = qi.kr - qr.ki streamed to g_S, with
//         online row max/sum of SCALE*S for both softmaxes.
// Pass 2: re-read S, P = exp(SCALE*S - m)/l written in place (per-head aw),
//         accumulate attn_r = Pr@Vr + Pi@Vi, attn_i = Pi@Vr - Pr@Vi.
// ============================================================================
__global__ __launch_bounds__(256)
void attn_kernel()
{
    extern __shared__ float smbuf[];
    float* Qt_r  = smbuf;                 // [64 d][65 row] transposed
    float* Qt_i  = Qt_r + 64*65;
    float* KV_r  = Qt_i + 64*65;          // K: [d][68 col] transposed / V: [s][68 d]
    float* KV_i  = KV_r + 64*68;
    float* St_r  = KV_i + 64*68;          // pass1: S stage [row][65 col]; pass2: P^T [col][65 row]
    float* St_i  = St_r + 64*65;
    float* sm_mr = St_i + 64*65;          // [64]
    float* sm_lr = sm_mr + 64;
    float* sm_mi = sm_lr + 64;
    float* sm_li = sm_mi + 64;

    const int tid = threadIdx.x;
    const int tx4 = (tid & 15) * 4;
    const int ty4 = (tid >> 4) * 4;
    const int bh  = blockIdx.x;
    const int t0  = blockIdx.y * 64;

    if (tid < 64) {
        sm_mr[tid] = -1e30f; sm_lr[tid] = 0.f;
        sm_mi[tid] = -1e30f; sm_li[tid] = 0.f;
    }

    // load Q tile transposed
    {
        const float* gq_r = g_hr + (size_t)(bh * 1024 + t0) * 64;
        const float* gq_i = g_hi + (size_t)(bh * 1024 + t0) * 64;
        for (int idx = tid; idx < 1024; idx += 256) {
            int r  = idx >> 4;
            int q4 = (idx & 15) << 2;
            float4 v = *(const float4*)(gq_r + r * 64 + q4);
            Qt_r[(q4+0)*65 + r] = v.x; Qt_r[(q4+1)*65 + r] = v.y;
            Qt_r[(q4+2)*65 + r] = v.z; Qt_r[(q4+3)*65 + r] = v.w;
            v = *(const float4*)(gq_i + r * 64 + q4);
            Qt_i[(q4+0)*65 + r] = v.x; Qt_i[(q4+1)*65 + r] = v.y;
            Qt_i[(q4+2)*65 + r] = v.z; Qt_i[(q4+3)*65 + r] = v.w;
        }
    }
    __syncthreads();

    const size_t srowbase = (size_t)(bh * 1024 + t0);

    // ---------------- pass 1 ----------------
    for (int st = 0; st < 16; st++) {
        const int s0 = st * 64;
        const float* gk_r = g_hr + HEADS + (size_t)(bh * 1024 + s0) * 64;
        const float* gk_i = g_hi + HEADS + (size_t)(bh * 1024 + s0) * 64;
        for (int idx = tid; idx < 1024; idx += 256) {
            int c  = idx >> 4;
            int q4 = (idx & 15) << 2;
            float4 v = *(const float4*)(gk_r + c * 64 + q4);
            KV_r[(q4+0)*68 + c] = v.x; KV_r[(q4+1)*68 + c] = v.y;
            KV_r[(q4+2)*68 + c] = v.z; KV_r[(q4+3)*68 + c] = v.w;
            v = *(const float4*)(gk_i + c * 64 + q4);
            KV_i[(q4+0)*68 + c] = v.x; KV_i[(q4+1)*68 + c] = v.y;
            KV_i[(q4+2)*68 + c] = v.z; KV_i[(q4+3)*68 + c] = v.w;
        }
        __syncthreads();

        float sr[4][4] = {}, si[4][4] = {};
        #pragma unroll 8
        for (int d = 0; d < 64; d++) {
            float qr[4], qi[4], kr[4], ki[4];
            #pragma unroll
            for (int u = 0; u < 4; u++) {
                qr[u] = Qt_r[d*65 + ty4+u];  qi[u] = Qt_i[d*65 + ty4+u];
                kr[u] = KV_r[d*68 + tx4+u];  ki[u] = KV_i[d*68 + tx4+u];
            }
            #pragma unroll
            for (int i = 0; i < 4; i++)
                #pragma unroll
                for (int j = 0; j < 4; j++) {
                    sr[i][j] += qr[i]*kr[j] + qi[i]*ki[j];
                    si[i][j] += qi[i]*kr[j] - qr[i]*ki[j];
                }
        }

        // stream S to scratch + stage for row stats
        #pragma unroll
        for (int i = 0; i < 4; i++) {
            size_t base = (srowbase + ty4 + i) * 1024 + s0 + tx4;
            *(float4*)(g_S + base)        = make_float4(sr[i][0], sr[i][1], sr[i][2], sr[i][3]);
            *(float4*)(g_S + SOFF + base) = make_float4(si[i][0], si[i][1], si[i][2], si[i][3]);
            #pragma unroll
            for (int j = 0; j < 4; j++) {
                St_r[(ty4+i)*65 + tx4+j] = sr[i][j];
                St_i[(ty4+i)*65 + tx4+j] = si[i][j];
            }
        }
        __syncthreads();

        // online max/sum update (warps 0-1: real, warps 2-3: imag)
        if (tid < 128) {
            int row = tid & 63;
            float* St = (tid < 64) ? St_r : St_i;
            float* Ms = (tid < 64) ? sm_mr : sm_mi;
            float* Ls = (tid < 64) ? sm_lr : sm_li;
            float m_old = Ms[row], l_old = Ls[row];
            float tmax = -1e30f;
            for (int c = 0; c < 64; c++) tmax = fmaxf(tmax, St[row*65 + c]);
            float m_new = fmaxf(m_old, tmax * SCALE);
            float s = 0.f;
            for (int c = 0; c < 64; c++) s += __expf(St[row*65 + c] * SCALE - m_new);
            Ls[row] = l_old * __expf(m_old - m_new) + s;
            Ms[row] = m_new;
        }
        __syncthreads();
    }

    if (tid < 64) { sm_lr[tid] = 1.f / sm_lr[tid]; sm_li[tid] = 1.f / sm_li[tid]; }
    __syncthreads();

    // ---------------- pass 2 ----------------
    float accR[4][4] = {}, accI[4][4] = {};

    for (int st = 0; st < 16; st++) {
        const int s0 = st * 64;
        const float* gv_r = g_hr + 2u*HEADS + (size_t)(bh * 1024 + s0) * 64;
        const float* gv_i = g_hi + 2u*HEADS + (size_t)(bh * 1024 + s0) * 64;
        for (int idx = tid; idx < 1024; idx += 256) {
            int s  = idx >> 4;
            int q4 = (idx & 15) << 2;
            *(float4*)(KV_r + s*68 + q4) = *(const float4*)(gv_r + s * 64 + q4);
            *(float4*)(KV_i + s*68 + q4) = *(const float4*)(gv_i + s * 64 + q4);
        }

        #pragma unroll
        for (int i = 0; i < 4; i++) {
            int r = ty4 + i;
            size_t base = (srowbase + r) * 1024 + s0 + tx4;
            float4 vr = *(const float4*)(g_S + base);
            float4 vi = *(const float4*)(g_S + SOFF + base);
            float mr = sm_mr[r], lrv = sm_lr[r];
            float mi = sm_mi[r], liv = sm_li[r];
            float4 pr, pi;
            pr.x = __expf(vr.x*SCALE - mr) * lrv;  pr.y = __expf(vr.y*SCALE - mr) * lrv;
            pr.z = __expf(vr.z*SCALE - mr) * lrv;  pr.w = __expf(vr.w*SCALE - mr) * lrv;
            pi.x = __expf(vi.x*SCALE - mi) * liv;  pi.y = __expf(vi.y*SCALE - mi) * liv;
            pi.z = __expf(vi.z*SCALE - mi) * liv;  pi.w = __expf(vi.w*SCALE - mi) * liv;
            *(float4*)(g_S + base)        = pr;    // per-head aw, in place
            *(float4*)(g_S + SOFF + base) = pi;
            // stage P transposed: [col][row]
            St_r[(tx4+0)*65 + r] = pr.x;  St_r[(tx4+1)*65 + r] = pr.y;
            St_r[(tx4+2)*65 + r] = pr.z;  St_r[(tx4+3)*65 + r] = pr.w;
            St_i[(tx4+0)*65 + r] = pi.x;  St_i[(tx4+1)*65 + r] = pi.y;
            St_i[(tx4+2)*65 + r] = pi.z;  St_i[(tx4+3)*65 + r] = pi.w;
        }
        __syncthreads();

        #pragma unroll 4
        for (int s = 0; s < 64; s++) {
            float prf[4], pif[4], vrf[4], vif[4];
            #pragma unroll
            for (int u = 0; u < 4; u++) {
                prf[u] = St_r[s*65 + ty4+u];
                pif[u] = St_i[s*65 + ty4+u];
                vrf[u] = KV_r[s*68 + tx4+u];
                vif[u] = KV_i[s*68 + tx4+u];
            }
            #pragma unroll
            for (int i = 0; i < 4; i++)
                #pragma unroll
                for (int j = 0; j < 4; j++) {
                    accR[i][j] += prf[i]*vrf[j] + pif[i]*vif[j];
                    accI[i][j] += pif[i]*vrf[j] - prf[i]*vif[j];
                }
        }
        __syncthreads();
    }

    // write attn in [t*B+b][E] layout (ready for output GEMM)
    const int b = bh >> 3, h = bh & 7;
    #pragma unroll
    for (int i = 0; i < 4; i++) {
        int t = t0 + ty4 + i;
        size_t o = (size_t)(t * 8 + b) * 512 + h * 64 + tx4;
        *(float4*)(g_attn + o)       = make_float4(accR[i][0], accR[i][1], accR[i][2], accR[i][3]);
        *(float4*)(g_attn + ATT + o) = make_float4(accI[i][0], accI[i][1], accI[i][2], accI[i][3]);
    }
}

// ============================================================================
// Head-average of attention weights into d_out aw region: [2][B][T][T]
// ============================================================================
__global__ __launch_bounds__(256)
void avg_kernel(float* __restrict__ dout)
{
    unsigned q = blockIdx.x * 256u + threadIdx.x;   // 0 .. 2097151 (each does 4 s)
    int s4 = (q & 255) << 2;
    int t  = (q >> 8) & 1023;
    int b  = q >> 18;
    float4 ar = make_float4(0.f, 0.f, 0.f, 0.f);
    float4 ai = make_float4(0.f, 0.f, 0.f, 0.f);
    #pragma unroll
    for (int h = 0; h < 8; h++) {
        size_t base = (size_t)((b * 8 + h) * 1024 + t) * 1024 + s4;
        float4 vr = *(const float4*)(g_S + base);
        float4 vi = *(const float4*)(g_S + SOFF + base);
        ar.x += vr.x; ar.y += vr.y; ar.z += vr.z; ar.w += vr.w;
        ai.x += vi.x; ai.y += vi.y; ai.z += vi.z; ai.w += vi.w;
    }
    const float inv = 0.125f;
    ar.x *= inv; ar.y *= inv; ar.z *= inv; ar.w *= inv;
    ai.x *= inv; ai.y *= inv; ai.z *= inv; ai.w *= inv;
    size_t o = (size_t)(b * 1024 + t) * 1024 + s4;
    *(float4*)(dout + AW0 + o) = ar;
    *(float4*)(dout + AWI + o) = ai;
}

// ============================================================================
extern "C" void kernel_launch(void* const* d_in, const int* in_sizes, int n_in,
                              void* d_out, int out_size)
{
    (void)in_sizes; (void)n_in; (void)out_size;
    const float* qr     = (const float*)d_in[0];
    const float* qi     = (const float*)d_in[1];
    const float* Wqkv_r = (const float*)d_in[2];
    const float* Wqkv_i = (const float*)d_in[3];
    const float* bqkv_r = (const float*)d_in[4];
    const float* bqkv_i = (const float*)d_in[5];
    const float* Wout_r = (const float*)d_in[6];
    const float* Wout_i = (const float*)d_in[7];
    const float* bout_r = (const float*)d_in[8];
    const float* bout_i = (const float*)d_in[9];
    float* out = (float*)d_out;

    cudaFuncSetAttribute(attn_kernel, cudaFuncAttributeMaxDynamicSharedMemorySize, 102400);

    // 1) QKV complex linear, scattered into head layout
    cgemm64<<<dim3(24, 128), 256>>>(qr, qi, Wqkv_r, Wqkv_i, bqkv_r, bqkv_i,
                                    nullptr, nullptr, 1536, 512, 1);
    // 2) fused complex attention (scores -> softmax -> PV), per-head aw in g_S
    attn_kernel<<<dim3(64, 16), 256, 102400>>>();
    // 3) head-averaged attention weights -> d_out aw region
    avg_kernel<<<8192, 256>>>(out);
    // 4) output complex linear -> d_out out region
    cgemm64<<<dim3(8, 128), 256>>>(nullptr, nullptr, Wout_r, Wout_i, bout_r, bout_i,
                                   out, out + OUT_I, 512, 512, 0);
}

// round 2
// speedup vs baseline: 1.0347x; 1.0347x over previous
#include <cuda_runtime.h>
#include <math.h>

#define SCALE 0.125f      // D^-0.5

#define HEADS 4194304u    // 64*1024*64   (one of q/k/v, one component)
#define SOFF  67108864u   // 64*1024*1024 (S scratch per component)
#define ATT   4194304u    // 8192*512
#define OUT_I 4194304u    // imag offset of out stack in d_out
#define AW0   8388608u    // aw region start in d_out
#define AWI   16777216u   // aw imag start in d_out

// -------- scratch (static __device__ arrays: allocation-free) ----------------
__device__ float g_hr[3u * HEADS];   // [part(q,k,v)][bh][t][d] real
__device__ float g_hi[3u * HEADS];   // imag
__device__ float g_S[2u * SOFF];     // [comp][bh][t][s] scores -> probs
__device__ float g_attn[2u * ATT];   // [comp][t*B+b][E] attn output

// ============================================================================
// Complex GEMM: C = A @ B^T (+bias), A:[M,K], B:[N,K] row-major.
// 128x64 tile, BK=16, 256 threads, 8x4 microtile, float4 fragment LDS.
// epi==0: write Cr/Ci (ld=N).  epi==1: scatter into g_hr/g_hi head layout.
// Ar==nullptr -> A = g_attn halves.
// ============================================================================
__global__ __launch_bounds__(256, 2)
void cgemm128(const float* __restrict__ Ar, const float* __restrict__ Ai,
              const float* __restrict__ Br, const float* __restrict__ Bi,
              const float* __restrict__ bias_r, const float* __restrict__ bias_i,
              float* __restrict__ Cr, float* __restrict__ Ci,
              int N, int K, int epi)
{
    __shared__ __align__(16) float As_r[16][132], As_i[16][132];
    __shared__ __align__(16) float Bs_r[16][68],  Bs_i[16][68];

    if (Ar == nullptr) { Ar = g_attn; Ai = g_attn + ATT; }

    const int tid  = threadIdx.x;
    const int tx   = tid & 15;           // col group: 4 cols
    const int ty   = tid >> 4;           // row group: 8 rows
    const int row0 = blockIdx.y * 128;
    const int col0 = blockIdx.x * 64;

    const int lar = tid >> 1;            // A loader row 0..127
    const int lak = (tid & 1) * 8;       // A loader k-half
    const int lbr = tid >> 2;            // B loader row 0..63
    const int lbk = (tid & 3) * 4;       // B loader k quarter

    const float* pAr = Ar + (size_t)(row0 + lar) * K + lak;
    const float* pAi = Ai + (size_t)(row0 + lar) * K + lak;
    const float* pBr = Br + (size_t)(col0 + lbr) * K + lbk;
    const float* pBi = Bi + (size_t)(col0 + lbr) * K + lbk;

    float accr[8][4] = {}, acci[8][4] = {};

    for (int kt = 0; kt < K; kt += 16) {
        float4 a0 = *(const float4*)(pAr + kt);
        float4 a1 = *(const float4*)(pAr + kt + 4);
        float4 a2 = *(const float4*)(pAi + kt);
        float4 a3 = *(const float4*)(pAi + kt + 4);
        float4 b0 = *(const float4*)(pBr + kt);
        float4 b1 = *(const float4*)(pBi + kt);
        __syncthreads();   // previous iteration's readers done
        As_r[lak+0][lar]=a0.x; As_r[lak+1][lar]=a0.y; As_r[lak+2][lar]=a0.z; As_r[lak+3][lar]=a0.w;
        As_r[lak+4][lar]=a1.x; As_r[lak+5][lar]=a1.y; As_r[lak+6][lar]=a1.z; As_r[lak+7][lar]=a1.w;
        As_i[lak+0][lar]=a2.x; As_i[lak+1][lar]=a2.y; As_i[lak+2][lar]=a2.z; As_i[lak+3][lar]=a2.w;
        As_i[lak+4][lar]=a3.x; As_i[lak+5][lar]=a3.y; As_i[lak+6][lar]=a3.z; As_i[lak+7][lar]=a3.w;
        Bs_r[lbk+0][lbr]=b0.x; Bs_r[lbk+1][lbr]=b0.y; Bs_r[lbk+2][lbr]=b0.z; Bs_r[lbk+3][lbr]=b0.w;
        Bs_i[lbk+0][lbr]=b1.x; Bs_i[lbk+1][lbr]=b1.y; Bs_i[lbk+2][lbr]=b1.z; Bs_i[lbk+3][lbr]=b1.w;
        __syncthreads();

        #pragma unroll 8
        for (int kk = 0; kk < 16; kk++) {
            float arf[8], aif[8], brf[4], bif[4];
            *(float4*)(arf)   = *(const float4*)&As_r[kk][ty*8];
            *(float4*)(arf+4) = *(const float4*)&As_r[kk][ty*8+4];
            *(float4*)(aif)   = *(const float4*)&As_i[kk][ty*8];
            *(float4*)(aif+4) = *(const float4*)&As_i[kk][ty*8+4];
            *(float4*)(brf)   = *(const float4*)&Bs_r[kk][tx*4];
            *(float4*)(bif)   = *(const float4*)&Bs_i[kk][tx*4];
            #pragma unroll
            for (int i = 0; i < 8; i++)
                #pragma unroll
                for (int j = 0; j < 4; j++) {
                    accr[i][j] += arf[i]*brf[j] - aif[i]*bif[j];
                    acci[i][j] += aif[i]*brf[j] + arf[i]*bif[j];
                }
        }
    }

    const int nb = col0 + tx * 4;
    float4 bsr = *(const float4*)(bias_r + nb);
    float4 bsi = *(const float4*)(bias_i + nb);
    #pragma unroll
    for (int i = 0; i < 8; i++) {
        int m = row0 + ty * 8 + i;
        float4 vr = make_float4(accr[i][0]+bsr.x, accr[i][1]+bsr.y, accr[i][2]+bsr.z, accr[i][3]+bsr.w);
        float4 vi = make_float4(acci[i][0]+bsi.x, acci[i][1]+bsi.y, acci[i][2]+bsi.z, acci[i][3]+bsi.w);
        if (epi == 0) {
            *(float4*)(Cr + (size_t)m * N + nb) = vr;
            *(float4*)(Ci + (size_t)m * N + nb) = vi;
        } else {
            // m = t*B + b ; nb = part*512 + h*64 + d  -> g_h[part][b*H+h][t][d]
            int t = m >> 3, b = m & 7;
            int part = nb >> 9;
            int e = nb & 511;
            int h = e >> 6, d = e & 63;
            size_t dst = (size_t)part * HEADS
                       + (size_t)((b * 8 + h) * 1024 + t) * 64 + d;
            *(float4*)(g_hr + dst) = vr;
            *(float4*)(g_hi + dst) = vi;
        }
    }
}

// ============================================================================
// Fused attention per (bh, 64-row q-tile).
// Pass 1: S complex scores streamed to g_S; row max/sum kept in REGISTERS
//         (online flash-style per thread), butterfly-combined once at the end.
// Pass 2: re-read S, P = exp(SCALE*S - m)*inv_l written in place (per-head aw),
//         accumulate attn via P@V complex mma.
// ============================================================================
__global__ __launch_bounds__(256, 2)
void attn_kernel()
{
    extern __shared__ __align__(16) float smbuf[];
    float* Qt_r  = smbuf;                 // [64 d][68] Q^T
    float* Qt_i  = Qt_r + 64*68;
    float* KV_r  = Qt_i + 64*68;          // pass1: K^T [d][68]; pass2: V [s][68]
    float* KV_i  = KV_r + 64*68;
    float* St_r  = KV_i + 64*68;          // pass2: P row-major [r][68]
    float* St_i  = St_r + 64*68;
    float* sm_m  = St_i + 64*68;          // [2][64]
    float* sm_li = sm_m + 128;            // [2][64] inverse sums

    const int tid = threadIdx.x;
    const int tx4 = (tid & 15) * 4;
    const int ty4 = (tid >> 4) * 4;
    const int bh  = blockIdx.x;
    const int t0  = blockIdx.y * 64;

    // load Q tile transposed
    {
        const float* gq_r = g_hr + (size_t)(bh * 1024 + t0) * 64;
        const float* gq_i = g_hi + (size_t)(bh * 1024 + t0) * 64;
        for (int idx = tid; idx < 1024; idx += 256) {
            int r  = idx >> 4;
            int q4 = (idx & 15) << 2;
            float4 v = *(const float4*)(gq_r + r * 64 + q4);
            Qt_r[(q4+0)*68 + r] = v.x; Qt_r[(q4+1)*68 + r] = v.y;
            Qt_r[(q4+2)*68 + r] = v.z; Qt_r[(q4+3)*68 + r] = v.w;
            v = *(const float4*)(gq_i + r * 64 + q4);
            Qt_i[(q4+0)*68 + r] = v.x; Qt_i[(q4+1)*68 + r] = v.y;
            Qt_i[(q4+2)*68 + r] = v.z; Qt_i[(q4+3)*68 + r] = v.w;
        }
    }

    const size_t srowbase = (size_t)(bh * 1024 + t0);

    float m_r[4], l_r[4], m_i[4], l_i[4];
    #pragma unroll
    for (int i = 0; i < 4; i++) { m_r[i] = m_i[i] = -1e30f; l_r[i] = l_i[i] = 0.f; }

    // ---------------- pass 1 ----------------
    for (int st = 0; st < 16; st++) {
        const int s0 = st * 64;
        const float* gk_r = g_hr + HEADS + (size_t)(bh * 1024 + s0) * 64;
        const float* gk_i = g_hi + HEADS + (size_t)(bh * 1024 + s0) * 64;
        __syncthreads();                  // previous tile's mma readers done (also covers Q load)
        for (int idx = tid; idx < 1024; idx += 256) {
            int c  = idx >> 4;
            int q4 = (idx & 15) << 2;
            float4 v = *(const float4*)(gk_r + c * 64 + q4);
            KV_r[(q4+0)*68 + c] = v.x; KV_r[(q4+1)*68 + c] = v.y;
            KV_r[(q4+2)*68 + c] = v.z; KV_r[(q4+3)*68 + c] = v.w;
            v = *(const float4*)(gk_i + c * 64 + q4);
            KV_i[(q4+0)*68 + c] = v.x; KV_i[(q4+1)*68 + c] = v.y;
            KV_i[(q4+2)*68 + c] = v.z; KV_i[(q4+3)*68 + c] = v.w;
        }
        __syncthreads();

        float sr[4][4] = {}, si[4][4] = {};
        #pragma unroll 8
        for (int d = 0; d < 64; d++) {
            float qr[4], qi[4], kr[4], ki[4];
            *(float4*)qr = *(const float4*)&Qt_r[d*68 + ty4];
            *(float4*)qi = *(const float4*)&Qt_i[d*68 + ty4];
            *(float4*)kr = *(const float4*)&KV_r[d*68 + tx4];
            *(float4*)ki = *(const float4*)&KV_i[d*68 + tx4];
            #pragma unroll
            for (int i = 0; i < 4; i++)
                #pragma unroll
                for (int j = 0; j < 4; j++) {
                    sr[i][j] += qr[i]*kr[j] + qi[i]*ki[j];
                    si[i][j] += qi[i]*kr[j] - qr[i]*ki[j];
                }
        }

        // inline register stats (flash-style online update, per thread)
        #pragma unroll
        for (int i = 0; i < 4; i++) {
            float tr = fmaxf(fmaxf(sr[i][0], sr[i][1]), fmaxf(sr[i][2], sr[i][3])) * SCALE;
            float mn = fmaxf(m_r[i], tr);
            float s  = __expf(sr[i][0]*SCALE - mn) + __expf(sr[i][1]*SCALE - mn)
                     + __expf(sr[i][2]*SCALE - mn) + __expf(sr[i][3]*SCALE - mn);
            l_r[i] = l_r[i] * __expf(m_r[i] - mn) + s;
            m_r[i] = mn;

            float ti = fmaxf(fmaxf(si[i][0], si[i][1]), fmaxf(si[i][2], si[i][3])) * SCALE;
            float mn2 = fmaxf(m_i[i], ti);
            float s2 = __expf(si[i][0]*SCALE - mn2) + __expf(si[i][1]*SCALE - mn2)
                     + __expf(si[i][2]*SCALE - mn2) + __expf(si[i][3]*SCALE - mn2);
            l_i[i] = l_i[i] * __expf(m_i[i] - mn2) + s2;
            m_i[i] = mn2;
        }

        // stream raw S to scratch
        #pragma unroll
        for (int i = 0; i < 4; i++) {
            size_t base = (srowbase + ty4 + i) * 1024 + s0 + tx4;
            *(float4*)(g_S + base)        = make_float4(sr[i][0], sr[i][1], sr[i][2], sr[i][3]);
            *(float4*)(g_S + SOFF + base) = make_float4(si[i][0], si[i][1], si[i][2], si[i][3]);
        }
    }

    // butterfly combine (m,l) across the 16 threads sharing each row group
    #pragma unroll
    for (int w = 1; w <= 8; w <<= 1) {
        #pragma unroll
        for (int i = 0; i < 4; i++) {
            float mo = __shfl_xor_sync(0xffffffffu, m_r[i], w);
            float lo = __shfl_xor_sync(0xffffffffu, l_r[i], w);
            float mn = fmaxf(m_r[i], mo);
            l_r[i] = l_r[i]*__expf(m_r[i]-mn) + lo*__expf(mo-mn);
            m_r[i] = mn;
            mo = __shfl_xor_sync(0xffffffffu, m_i[i], w);
            lo = __shfl_xor_sync(0xffffffffu, l_i[i], w);
            mn = fmaxf(m_i[i], mo);
            l_i[i] = l_i[i]*__expf(m_i[i]-mn) + lo*__expf(mo-mn);
            m_i[i] = mn;
        }
    }
    if ((tid & 15) == 0) {
        #pragma unroll
        for (int i = 0; i < 4; i++) {
            sm_m[ty4+i]       = m_r[i];
            sm_m[64+ty4+i]    = m_i[i];
            sm_li[ty4+i]      = 1.f / l_r[i];
            sm_li[64+ty4+i]   = 1.f / l_i[i];
        }
    }

    // ---------------- pass 2 ----------------
    float accR[4][4] = {}, accI[4][4] = {};

    for (int st = 0; st < 16; st++) {
        const int s0 = st * 64;
        const float* gv_r = g_hr + 2u*HEADS + (size_t)(bh * 1024 + s0) * 64;
        const float* gv_i = g_hi + 2u*HEADS + (size_t)(bh * 1024 + s0) * 64;
        __syncthreads();                  // prev mma readers done; also fences sm_m/sm_li
        for (int idx = tid; idx < 1024; idx += 256) {
            int s  = idx >> 4;
            int q4 = (idx & 15) << 2;
            *(float4*)(KV_r + s*68 + q4) = *(const float4*)(gv_r + s * 64 + q4);
            *(float4*)(KV_i + s*68 + q4) = *(const float4*)(gv_i + s * 64 + q4);
        }

        #pragma unroll
        for (int i = 0; i < 4; i++) {
            int r = ty4 + i;
            size_t base = (srowbase + r) * 1024 + s0 + tx4;
            float4 vr = *(const float4*)(g_S + base);
            float4 vi = *(const float4*)(g_S + SOFF + base);
            float mr = sm_m[r],    lrv = sm_li[r];
            float mi = sm_m[64+r], liv = sm_li[64+r];
            float4 pr, pi;
            pr.x = __expf(vr.x*SCALE - mr) * lrv;  pr.y = __expf(vr.y*SCALE - mr) * lrv;
            pr.z = __expf(vr.z*SCALE - mr) * lrv;  pr.w = __expf(vr.w*SCALE - mr) * lrv;
            pi.x = __expf(vi.x*SCALE - mi) * liv;  pi.y = __expf(vi.y*SCALE - mi) * liv;
            pi.z = __expf(vi.z*SCALE - mi) * liv;  pi.w = __expf(vi.w*SCALE - mi) * liv;
            *(float4*)(g_S + base)        = pr;    // per-head aw, normalized, in place
            *(float4*)(g_S + SOFF + base) = pi;
            *(float4*)(St_r + r*68 + tx4) = pr;    // row-major stage for mma
            *(float4*)(St_i + r*68 + tx4) = pi;
        }
        __syncthreads();

        #pragma unroll 4
        for (int s = 0; s < 64; s++) {
            float prf[4], pif[4], vrf[4], vif[4];
            #pragma unroll
            for (int u = 0; u < 4; u++) {
                prf[u] = St_r[(ty4+u)*68 + s];
                pif[u] = St_i[(ty4+u)*68 + s];
            }
            *(float4*)vrf = *(const float4*)&KV_r[s*68 + tx4];
            *(float4*)vif = *(const float4*)&KV_i[s*68 + tx4];
            #pragma unroll
            for (int i = 0; i < 4; i++)
                #pragma unroll
                for (int j = 0; j < 4; j++) {
                    accR[i][j] += prf[i]*vrf[j] + pif[i]*vif[j];
                    accI[i][j] += pif[i]*vrf[j] - prf[i]*vif[j];
                }
        }
    }

    // write attn in [t*B+b][E] layout (ready for output GEMM)
    const int b = bh >> 3, h = bh & 7;
    #pragma unroll
    for (int i = 0; i < 4; i++) {
        int t = t0 + ty4 + i;
        size_t o = (size_t)(t * 8 + b) * 512 + h * 64 + tx4;
        *(float4*)(g_attn + o)       = make_float4(accR[i][0], accR[i][1], accR[i][2], accR[i][3]);
        *(float4*)(g_attn + ATT + o) = make_float4(accI[i][0], accI[i][1], accI[i][2], accI[i][3]);
    }
}

// ============================================================================
// Head-average of attention weights into d_out aw region: [2][B][T][T]
// ============================================================================
__global__ __launch_bounds__(256)
void avg_kernel(float* __restrict__ dout)
{
    unsigned q = blockIdx.x * 256u + threadIdx.x;   // each thread does 4 s
    int s4 = (q & 255) << 2;
    int t  = (q >> 8) & 1023;
    int b  = q >> 18;
    float4 ar = make_float4(0.f, 0.f, 0.f, 0.f);
    float4 ai = make_float4(0.f, 0.f, 0.f, 0.f);
    #pragma unroll
    for (int h = 0; h < 8; h++) {
        size_t base = (size_t)((b * 8 + h) * 1024 + t) * 1024 + s4;
        float4 vr = *(const float4*)(g_S + base);
        float4 vi = *(const float4*)(g_S + SOFF + base);
        ar.x += vr.x; ar.y += vr.y; ar.z += vr.z; ar.w += vr.w;
        ai.x += vi.x; ai.y += vi.y; ai.z += vi.z; ai.w += vi.w;
    }
    const float inv = 0.125f;
    ar.x *= inv; ar.y *= inv; ar.z *= inv; ar.w *= inv;
    ai.x *= inv; ai.y *= inv; ai.z *= inv; ai.w *= inv;
    size_t o = (size_t)(b * 1024 + t) * 1024 + s4;
    *(float4*)(dout + AW0 + o) = ar;
    *(float4*)(dout + AWI + o) = ai;
}

// ============================================================================
extern "C" void kernel_launch(void* const* d_in, const int* in_sizes, int n_in,
                              void* d_out, int out_size)
{
    (void)in_sizes; (void)n_in; (void)out_size;
    const float* qr     = (const float*)d_in[0];
    const float* qi     = (const float*)d_in[1];
    const float* Wqkv_r = (const float*)d_in[2];
    const float* Wqkv_i = (const float*)d_in[3];
    const float* bqkv_r = (const float*)d_in[4];
    const float* bqkv_i = (const float*)d_in[5];
    const float* Wout_r = (const float*)d_in[6];
    const float* Wout_i = (const float*)d_in[7];
    const float* bout_r = (const float*)d_in[8];
    const float* bout_i = (const float*)d_in[9];
    float* out = (float*)d_out;

    cudaFuncSetAttribute(attn_kernel, cudaFuncAttributeMaxDynamicSharedMemorySize, 105984);

    // 1) QKV complex linear, scattered into head layout
    cgemm128<<<dim3(24, 64), 256>>>(qr, qi, Wqkv_r, Wqkv_i, bqkv_r, bqkv_i,
                                    nullptr, nullptr, 1536, 512, 1);
    // 2) fused complex attention (scores -> softmax -> PV), per-head aw in g_S
    attn_kernel<<<dim3(64, 16), 256, 105984>>>();
    // 3) head-averaged attention weights -> d_out aw region
    avg_kernel<<<8192, 256>>>(out);
    // 4) output complex linear -> d_out out region
    cgemm128<<<dim3(8, 64), 256>>>(nullptr, nullptr, Wout_r, Wout_i, bout_r, bout_i,
                                   out, out + OUT_I, 512, 512, 0);
}